// round 2
// baseline (speedup 1.0000x reference)
#include <cuda_runtime.h>
#include <stdint.h>

#define NB 8
#define NANCH 13343
#define TOPK 1000
#define CAND 2048
#define NCLS 80

// ---------------- scratch (device globals; no allocation allowed) ----------------
__device__ unsigned g_sbits[NB * NANCH];
__device__ int      g_cls[NB * NANCH];
__device__ float    g_bx1[NB * NANCH], g_by1[NB * NANCH], g_bx2[NB * NANCH], g_by2[NB * NANCH];

__device__ float    g_tsc[NB * 1024];
__device__ int      g_tcl[NB * 1024];
__device__ float    g_tx1[NB * 1024], g_ty1[NB * 1024], g_tx2[NB * 1024], g_ty2[NB * 1024];
__device__ float    g_ox1[NB * 1024], g_oy1[NB * 1024], g_ox2[NB * 1024], g_oy2[NB * 1024], g_oar[NB * 1024];

__device__ unsigned      g_mask[NB * TOPK * 32];
__device__ unsigned char g_rnz[NB * TOPK];

struct Ptrs {
    const float* cls[5];
    const float* cnt[5];
    const float* reg[5];
};

// ---------------- XLA-compatible sigmoid ----------------
// XLA lowers logistic(x) = 0.5 + 0.5*tanh(0.5*x); tanh via EmitFastTanh:
// clamp to +-7.90531110763549805, passthrough for |x| < 0.0004, rational
// polynomial in x^2. Crucially the Horner chains are emitted as SEPARATE
// mul+add (no fma contraction) — replicated here with __fmul_rn/__fadd_rn
// so nvcc cannot re-contract them.
__device__ __forceinline__ float xla_tanh(float x) {
    float xc = fminf(fmaxf(x, -7.90531110763549805f), 7.90531110763549805f);
    float x2 = __fmul_rn(xc, xc);
    float p = -2.76076847742355e-16f;
    p = __fadd_rn(__fmul_rn(p, x2), 2.00018790482477e-13f);
    p = __fadd_rn(__fmul_rn(p, x2), -8.60467152213735e-11f);
    p = __fadd_rn(__fmul_rn(p, x2), 5.12229709037114e-08f);
    p = __fadd_rn(__fmul_rn(p, x2), 1.48572235717979e-05f);
    p = __fadd_rn(__fmul_rn(p, x2), 6.37261928875436e-04f);
    p = __fadd_rn(__fmul_rn(p, x2), 4.89352455891786e-03f);
    p = __fmul_rn(xc, p);
    float q = 1.19825839466702e-06f;
    q = __fadd_rn(__fmul_rn(q, x2), 1.18534705686654e-04f);
    q = __fadd_rn(__fmul_rn(q, x2), 2.26843463243900e-03f);
    q = __fadd_rn(__fmul_rn(q, x2), 4.89352518554385e-03f);
    float r = __fdiv_rn(p, q);
    return (fabsf(x) < 0.0004f) ? x : r;
}
__device__ __forceinline__ float xla_sigmoid(float x) {
    return __fadd_rn(0.5f, __fmul_rn(0.5f, xla_tanh(__fmul_rn(0.5f, x))));
}

// ---------------- kernel 1: per-anchor scores / classes / boxes ----------------
__global__ void k_score(Ptrs P) {
    int t = blockIdx.x * blockDim.x + threadIdx.x;
    if (t >= NB * NANCH) return;
    int b = t / NANCH;
    int a = t - b * NANCH;

    int l, p;
    if (a < 10000)      { l = 0; p = a; }
    else if (a < 12500) { l = 1; p = a - 10000; }
    else if (a < 13125) { l = 2; p = a - 12500; }
    else if (a < 13294) { l = 3; p = a - 13125; }
    else                { l = 4; p = a - 13294; }

    const int wlv[5] = {100, 50, 25, 13, 7};
    const int hwv[5] = {10000, 2500, 625, 169, 49};
    const int stv[5] = {8, 16, 32, 64, 128};
    int w = wlv[l], HW = hwv[l], s = stv[l];
    int y = p / w, x = p - y * w;
    float cx = (float)(x * s + (s >> 1));
    float cy = (float)(y * s + (s >> 1));

    const float* cls = P.cls[l];
    const float* cnt = P.cnt[l];
    const float* reg = P.reg[l];

    // max/argmax over sigmoid(logits) — computed on sigmoid values to exactly
    // replicate jnp.max/jnp.argmax over cls_preds (first-max semantics).
    float best = -__int_as_float(0x7f800000);  // -inf
    int bi = 0;
    const float* cp = cls + (size_t)b * NCLS * HW + p;
#pragma unroll 4
    for (int c = 0; c < NCLS; c++) {
        float sv = xla_sigmoid(cp[(size_t)c * HW]);
        if (sv > best) { best = sv; bi = c; }
    }
    float cv = xla_sigmoid(cnt[(size_t)b * HW + p]);
    float score = sqrtf(__fmul_rn(best, cv));

    int o = b * NANCH + a;
    g_sbits[o] = __float_as_uint(score);
    g_cls[o] = bi + 1;

    float r0 = reg[((size_t)b * 4 + 0) * HW + p];
    float r1 = reg[((size_t)b * 4 + 1) * HW + p];
    float r2 = reg[((size_t)b * 4 + 2) * HW + p];
    float r3 = reg[((size_t)b * 4 + 3) * HW + p];
    g_bx1[o] = __fsub_rn(cx, r0);
    g_by1[o] = __fsub_rn(cy, r1);
    g_bx2[o] = __fadd_rn(cx, r2);
    g_by2[o] = __fadd_rn(cy, r3);
}

// ---------------- kernel 2: per-batch exact top-1000 (radix select + small sort) ----------------
__global__ __launch_bounds__(1024) void k_topk() {
    __shared__ unsigned s_hist[1024];
    __shared__ unsigned long long s_cand[CAND];
    __shared__ unsigned s_B, s_above, s_cnt;
    __shared__ float s_red[32];
    __shared__ float s_max;

    int b = blockIdx.x;
    int tid = threadIdx.x;
    int lane = tid & 31, wid = tid >> 5;
    const unsigned* sb = g_sbits + b * NANCH;

    // 3-pass radix histogram on the (positive) float score bits to find the
    // exact bit-pattern of the 1000th-largest score.
    unsigned prefix = 0;
    unsigned target = TOPK;
    for (int pass = 0; pass < 3; pass++) {
        int shift = 20 - 10 * pass;
        s_hist[tid] = 0;
        __syncthreads();
        for (int i = tid; i < NANCH; i += 1024) {
            unsigned v = sb[i];
            bool in = (pass == 0) || ((v >> (shift + 10)) == prefix);
            if (in) atomicAdd(&s_hist[(v >> shift) & 1023], 1u);
        }
        __syncthreads();
        // inclusive suffix sum (Hillis-Steele)
        for (int off = 1; off < 1024; off <<= 1) {
            unsigned v = s_hist[tid] + ((tid + off < 1024) ? s_hist[tid + off] : 0u);
            __syncthreads();
            s_hist[tid] = v;
            __syncthreads();
        }
        unsigned mine = s_hist[tid];
        unsigned nxt = (tid < 1023) ? s_hist[tid + 1] : 0u;
        if (mine >= target && nxt < target) { s_B = tid; s_above = nxt; }
        __syncthreads();
        prefix = (prefix << 10) | s_B;
        target = target - s_above;
        __syncthreads();
    }
    unsigned T = prefix;  // bits of the 1000th largest score

    // gather all candidates with bits >= T
    if (tid == 0) s_cnt = 0;
    __syncthreads();
    for (int i = tid; i < NANCH; i += 1024) {
        unsigned v = sb[i];
        if (v >= T) {
            unsigned pos = atomicAdd(&s_cnt, 1u);
            if (pos < CAND)
                s_cand[pos] = ((unsigned long long)v << 32) | (unsigned)(~i);
        }
    }
    __syncthreads();
    int n = (int)min(s_cnt, (unsigned)CAND);
    for (int i = tid; i < CAND; i += 1024)
        if (i >= n) s_cand[i] = 0ULL;
    __syncthreads();

    // bitonic sort descending; key = (score_bits << 32) | ~idx  → stable ties by index
    for (int k = 2; k <= CAND; k <<= 1) {
        for (int j = k >> 1; j > 0; j >>= 1) {
            for (int i = tid; i < CAND; i += 1024) {
                int ixj = i ^ j;
                if (ixj > i) {
                    bool up = (i & k) == 0;
                    unsigned long long av = s_cand[i], bv = s_cand[ixj];
                    bool sw = up ? (av < bv) : (av > bv);
                    if (sw) { s_cand[i] = bv; s_cand[ixj] = av; }
                }
            }
            __syncthreads();
        }
    }

    // epilogue: gather top-1000, compute validity, max_coord, offset boxes + areas
    float m = -__int_as_float(0x7f800000);
    float sc = 0.f, x1 = 0.f, y1 = 0.f, x2 = 0.f, y2 = 0.f;
    int cl = 0;
    bool valid = false;
    if (tid < TOPK) {
        unsigned long long key = s_cand[tid];
        unsigned sbits = (unsigned)(key >> 32);
        int idx = (int)(~(unsigned)key);
        sc = __uint_as_float(sbits);
        int o = b * NANCH + idx;
        cl = g_cls[o];
        x1 = g_bx1[o]; y1 = g_by1[o]; x2 = g_bx2[o]; y2 = g_by2[o];
        valid = (sc >= 0.05f);
        int to = b * 1024 + tid;
        g_tsc[to] = sc; g_tcl[to] = cl;
        g_tx1[to] = x1; g_ty1[to] = y1; g_tx2[to] = x2; g_ty2[to] = y2;
        m = valid ? fmaxf(fmaxf(x1, y1), fmaxf(x2, y2)) : 0.0f;
    }
    // block max-reduce (1024 threads = 32 warps)
    for (int o = 16; o > 0; o >>= 1) m = fmaxf(m, __shfl_down_sync(0xffffffffu, m, o));
    if (lane == 0) s_red[wid] = m;
    __syncthreads();
    if (tid < 32) {
        float v = s_red[tid];
        for (int o = 16; o > 0; o >>= 1) v = fmaxf(v, __shfl_down_sync(0xffffffffu, v, o));
        if (tid == 0) s_max = v;
    }
    __syncthreads();
    float maxc = s_max;

    if (tid < TOPK) {
        float off = __fmul_rn((float)cl, __fadd_rn(maxc, 1.0f));
        float ox1 = __fadd_rn(x1, off);
        float oy1 = __fadd_rn(y1, off);
        float ox2 = __fadd_rn(x2, off);
        float oy2 = __fadd_rn(y2, off);
        float area = __fmul_rn(__fadd_rn(__fsub_rn(ox2, ox1), 1.0f),
                               __fadd_rn(__fsub_rn(oy2, oy1), 1.0f));
        int to = b * 1024 + tid;
        g_ox1[to] = ox1; g_oy1[to] = oy1; g_ox2[to] = ox2; g_oy2[to] = oy2;
        g_oar[to] = area;
    }
}

// ---------------- kernel 3a: upper-triangular suppression bitmask ----------------
__global__ void k_mask() {
    int gw = (blockIdx.x * blockDim.x + threadIdx.x) >> 5;
    int lane = threadIdx.x & 31;
    if (gw >= NB * TOPK) return;
    int b = gw / TOPK;
    int i = gw - b * TOPK;
    int base = b * 1024;

    float x1i = g_ox1[base + i], y1i = g_oy1[base + i];
    float x2i = g_ox2[base + i], y2i = g_oy2[base + i];
    float ai = g_oar[base + i];

    unsigned rowor = 0;
#pragma unroll 4
    for (int w = 0; w < 32; w++) {
        int j = w * 32 + lane;
        unsigned bit = 0;
        if (j > i && j < TOPK) {
            float xx1 = fmaxf(x1i, g_ox1[base + j]);
            float yy1 = fmaxf(y1i, g_oy1[base + j]);
            float xx2 = fminf(x2i, g_ox2[base + j]);
            float yy2 = fminf(y2i, g_oy2[base + j]);
            float iw = fmaxf(__fsub_rn(xx2, xx1), 0.0f);
            float ih = fmaxf(__fsub_rn(yy2, yy1), 0.0f);
            float inter = __fmul_rn(iw, ih);
            float uni = __fsub_rn(__fadd_rn(ai, g_oar[base + j]), inter);
            float iou = __fdiv_rn(inter, uni);
            bit = (iou > 0.6f) ? 1u : 0u;
        }
        unsigned word = __ballot_sync(0xffffffffu, bit);
        if (lane == 0) {
            g_mask[(b * TOPK + i) * 32 + w] = word;
            rowor |= word;
        }
    }
    if (lane == 0) g_rnz[b * TOPK + i] = (rowor != 0) ? 1 : 0;
}

// ---------------- kernel 3b: sparse greedy scan + output ----------------
__global__ void k_scan(float* out) {
    __shared__ unsigned s_valid[32], s_ne[32];
    __shared__ volatile unsigned s_removed[32];

    int b = blockIdx.x;
    int tid = threadIdx.x;
    int lane = tid & 31;

    for (int k = 0; k < 4; k++) {
        int t = k * 256 + tid;
        int v = 0, nz = 0;
        if (t < TOPK) {
            v = (g_tsc[b * 1024 + t] >= 0.05f) ? 1 : 0;
            nz = g_rnz[b * TOPK + t];
        }
        unsigned bv = __ballot_sync(0xffffffffu, v);
        unsigned bn = __ballot_sync(0xffffffffu, nz);
        if (lane == 0) { s_valid[t >> 5] = bv; s_ne[t >> 5] = bn; }
    }
    if (tid < 32) s_removed[tid] = 0;
    __syncthreads();

    // warp 0: greedy scan, visiting only valid & row-nonempty entries in order.
    // A row i can only set bits j > i, so ascending order is safe.
    if (tid < 32) {
        for (int w = 0; w < 32; ++w) {
            unsigned cand = s_valid[w] & s_ne[w];
            while (true) {
                unsigned rm = s_removed[w];
                unsigned act = cand & ~rm;
                if (!act) break;
                int bp = __ffs(act) - 1;
                cand &= ~(1u << bp);
                int i = w * 32 + bp;
                unsigned mrow = g_mask[(b * TOPK + i) * 32 + lane];
                s_removed[lane] = s_removed[lane] | mrow;
                __syncwarp();
            }
        }
    }
    __syncthreads();

    // write outputs: scores | classes | boxes (flattened tuple, float32)
    for (int k = 0; k < 4; k++) {
        int t = k * 256 + tid;
        if (t < TOPK) {
            unsigned rem = s_removed[t >> 5];
            bool keep = (((s_valid[t >> 5] >> (t & 31)) & 1u) != 0u) &&
                        (((rem >> (t & 31)) & 1u) == 0u);
            int to = b * 1024 + t;
            float sc = keep ? g_tsc[to] : 0.0f;
            float cf = keep ? (float)g_tcl[to] : 0.0f;
            out[b * TOPK + t] = sc;
            out[NB * TOPK + b * TOPK + t] = cf;
            float bx1 = keep ? g_tx1[to] : 0.0f;
            float by1 = keep ? g_ty1[to] : 0.0f;
            float bx2 = keep ? g_tx2[to] : 0.0f;
            float by2 = keep ? g_ty2[to] : 0.0f;
            size_t bo = (size_t)2 * NB * TOPK + ((size_t)(b * TOPK + t)) * 4;
            out[bo + 0] = bx1;
            out[bo + 1] = by1;
            out[bo + 2] = bx2;
            out[bo + 3] = by2;
        }
    }
}

// ---------------- launch ----------------
extern "C" void kernel_launch(void* const* d_in, const int* in_sizes, int n_in,
                              void* d_out, int out_size) {
    (void)in_sizes; (void)n_in; (void)out_size;
    Ptrs P;
    for (int i = 0; i < 5; i++) {
        P.cls[i] = (const float*)d_in[i];
        P.cnt[i] = (const float*)d_in[5 + i];
        P.reg[i] = (const float*)d_in[10 + i];
    }
    int total = NB * NANCH;
    k_score<<<(total + 255) / 256, 256>>>(P);
    k_topk<<<NB, 1024>>>();
    k_mask<<<(NB * TOPK * 32 + 255) / 256, 256>>>();
    k_scan<<<NB, 256>>>((float*)d_out);
}